// round 9
// baseline (speedup 1.0000x reference)
#include <cuda_runtime.h>
#include <math.h>

#define cB 64
#define cL 256
#define cE 256
#define cH 512
#define cM 256
#define cHD 64
#define cO 1024
#define cCI 512
#define cTO 768
#define EPS 1e-5f
#define NBLK 128

__device__ float g_h[2][cB][cH];
__device__ float g_c[cB][cH];
__device__ float g_ci[cB][cCI];
__device__ float g_outln[cB][cTO];
__device__ float g_head[cB][512];
__device__ float g_lnpart[32][cB][2];
__device__ unsigned g_cnt = 0;
__device__ unsigned g_gen = 0;

__device__ __forceinline__ float sigf(float x) { return 1.0f / (1.0f + expf(-x)); }

__device__ __forceinline__ void gsync() {
    __syncthreads();
    if (threadIdx.x == 0) {
        unsigned gen = *(volatile unsigned*)&g_gen;
        __threadfence();
        if (atomicAdd(&g_cnt, 1u) == NBLK - 1) {
            g_cnt = 0;
            __threadfence();
            *(volatile unsigned*)&g_gen = gen + 1;
        } else {
            while (*(volatile unsigned*)&g_gen == gen) {}
        }
        __threadfence();
    }
    __syncthreads();
}

__device__ __forceinline__ float brsum(float v, float* red) {
    int tid = threadIdx.x;
#pragma unroll
    for (int o = 16; o; o >>= 1) v += __shfl_xor_sync(0xffffffffu, v, o);
    if ((tid & 31) == 0) red[tid >> 5] = v;
    __syncthreads();
    if (tid == 0) { float s = 0.f; for (int i = 0; i < 8; ++i) s += red[i]; red[0] = s; }
    __syncthreads();
    float r = red[0];
    __syncthreads();
    return r;
}
__device__ __forceinline__ float brmax(float v, float* red) {
    int tid = threadIdx.x;
#pragma unroll
    for (int o = 16; o; o >>= 1) v = fmaxf(v, __shfl_xor_sync(0xffffffffu, v, o));
    if ((tid & 31) == 0) red[tid >> 5] = v;
    __syncthreads();
    if (tid == 0) { float s = red[0]; for (int i = 1; i < 8; ++i) s = fmaxf(s, red[i]); red[0] = s; }
    __syncthreads();
    float r = red[0];
    __syncthreads();
    return r;
}

__device__ __forceinline__ const float* headrow(int g, const float* Wrk, const float* Wwk,
                                                const float* Wws, const float* Wer,
                                                const float* Wad) {
    if (g < 256) return Wrk + (size_t)g * 512;
    if (g < 320) return Wwk + (size_t)(g - 256) * 512;
    if (g == 320) return Wws;
    if (g < 385) return Wer + (size_t)(g - 321) * 512;
    if (g < 449) return Wad + (size_t)(g - 385) * 512;
    return nullptr;
}

// gates GEMM tile [16 rows x 64 cols, K=1024] + LSTM + LN partials
__device__ void doA(int t, float* scr, const float* __restrict__ Wih,
                    const float* __restrict__ Whh, const float* __restrict__ bih,
                    const float* __restrict__ bhh) {
    int tid = threadIdx.x, jj = blockIdx.x & 31, mq = blockIdx.x >> 5;
    int u0 = jj * 16, cur = t & 1, nx = (t + 1) & 1;
    float* As = scr;         // [32][20]
    float* Ws = scr + 640;   // [32][68]
    int r = tid >> 4, c0 = (tid & 15) * 4;
    float acc[4] = {0.f, 0.f, 0.f, 0.f};
    for (int kt = 0; kt < 1024; kt += 32) {
        __syncthreads();
        if (tid < 128) {
            int rr = tid >> 3, k4 = (tid & 7) * 4;
            int B = mq * 16 + rr;
            const float* src = (kt < 512) ? &g_ci[B][kt + k4] : &g_h[cur][B][kt - 512 + k4];
            float4 v = *(const float4*)src;
            As[(k4 + 0) * 20 + rr] = v.x; As[(k4 + 1) * 20 + rr] = v.y;
            As[(k4 + 2) * 20 + rr] = v.z; As[(k4 + 3) * 20 + rr] = v.w;
        }
#pragma unroll
        for (int i = 0; i < 2; ++i) {
            int idx = tid + i * 256, cc = idx >> 3, k4 = (idx & 7) * 4;
            int wrow = (cc >> 4) * 512 + u0 + (cc & 15);
            const float* ws = (kt < 512) ? Wih + (size_t)wrow * 512 + kt + k4
                                         : Whh + (size_t)wrow * 512 + (kt - 512) + k4;
            float4 v = *(const float4*)ws;
            Ws[(k4 + 0) * 68 + cc] = v.x; Ws[(k4 + 1) * 68 + cc] = v.y;
            Ws[(k4 + 2) * 68 + cc] = v.z; Ws[(k4 + 3) * 68 + cc] = v.w;
        }
        __syncthreads();
#pragma unroll
        for (int k = 0; k < 32; ++k) {
            float a = As[k * 20 + r];
            float4 w = *(const float4*)&Ws[k * 68 + c0];
            acc[0] += a * w.x; acc[1] += a * w.y; acc[2] += a * w.z; acc[3] += a * w.w;
        }
    }
    __syncthreads();
    float* Cs = scr;  // [16][65]
#pragma unroll
    for (int j = 0; j < 4; ++j) Cs[r * 65 + c0 + j] = acc[j];
    __syncthreads();
    int b = tid >> 4, u = tid & 15;
    int B = mq * 16 + b, U = u0 + u;
    float gi = Cs[b * 65 + u]      + bih[U]        + bhh[U];
    float gf = Cs[b * 65 + 16 + u] + bih[512 + U]  + bhh[512 + U];
    float gg = Cs[b * 65 + 32 + u] + bih[1024 + U] + bhh[1024 + U];
    float go = Cs[b * 65 + 48 + u] + bih[1536 + U] + bhh[1536 + U];
    float cc = sigf(gf) * g_c[B][U] + sigf(gi) * tanhf(gg);
    float hh = sigf(go) * tanhf(cc);
    g_c[B][U] = cc;
    g_h[nx][B][U] = hh;
    float s1 = hh, s2 = hh * hh;
#pragma unroll
    for (int o = 8; o; o >>= 1) {
        s1 += __shfl_xor_sync(0xffffffffu, s1, o);
        s2 += __shfl_xor_sync(0xffffffffu, s2, o);
    }
    if (u == 0) { g_lnpart[jj][B][0] = s1; g_lnpart[jj][B][1] = s2; }
}

// proj: 16 output cols per block, 64 rows, K=768
__device__ void doProj(int p, int trow, float* scr, const float* __restrict__ Wproj,
                       const float* __restrict__ bproj, float* __restrict__ out) {
    int tid = threadIdx.x;
    float* As = scr;          // [32][68]
    float* Ws = scr + 2176;   // [32][20]
    int r0 = (tid >> 3) * 2, c0 = (tid & 7) * 2;
    float a00 = 0.f, a01 = 0.f, a10 = 0.f, a11 = 0.f;
    for (int kt = 0; kt < 768; kt += 32) {
        __syncthreads();
#pragma unroll
        for (int i = 0; i < 2; ++i) {
            int idx = tid + i * 256, rr = idx >> 3, k4 = (idx & 7) * 4;
            float4 v = *(const float4*)&g_outln[rr][kt + k4];
            As[(k4 + 0) * 68 + rr] = v.x; As[(k4 + 1) * 68 + rr] = v.y;
            As[(k4 + 2) * 68 + rr] = v.z; As[(k4 + 3) * 68 + rr] = v.w;
        }
        if (tid < 128) {
            int cc = tid >> 3, k4 = (tid & 7) * 4;
            float4 v = *(const float4*)&Wproj[(size_t)(16 * p + cc) * 768 + kt + k4];
            Ws[(k4 + 0) * 20 + cc] = v.x; Ws[(k4 + 1) * 20 + cc] = v.y;
            Ws[(k4 + 2) * 20 + cc] = v.z; Ws[(k4 + 3) * 20 + cc] = v.w;
        }
        __syncthreads();
#pragma unroll
        for (int k = 0; k < 32; ++k) {
            float2 a = *(const float2*)&As[k * 68 + r0];
            float2 w = *(const float2*)&Ws[k * 20 + c0];
            a00 += a.x * w.x; a01 += a.x * w.y; a10 += a.y * w.x; a11 += a.y * w.y;
        }
    }
    int col = 16 * p + c0;
    float b0 = bproj[col], b1 = bproj[col + 1];
    out[((size_t)(r0 + 0) * cL + trow) * cO + col]     = a00 + b0;
    out[((size_t)(r0 + 0) * cL + trow) * cO + col + 1] = a01 + b1;
    out[((size_t)(r0 + 1) * cL + trow) * cO + col]     = a10 + b0;
    out[((size_t)(r0 + 1) * cL + trow) * cO + col + 1] = a11 + b1;
}

// heads: 8 head-rows per block, 64 batch rows, K=512, LN(h) inline
__device__ void doHeads(int q, int nx, float* scr,
                        const float* __restrict__ lnhg, const float* __restrict__ lnhb,
                        const float* __restrict__ Wrk, const float* __restrict__ Wwk,
                        const float* __restrict__ Wws, const float* __restrict__ Wer,
                        const float* __restrict__ Wad) {
    int tid = threadIdx.x;
    float* As = scr;           // [32][68]
    float* Ws = scr + 2176;    // [32][12]
    float* smean = scr + 2560; // 64
    float* srstd = scr + 2624; // 64
    if (tid < 64) {
        float s = 0.f, s2 = 0.f;
        for (int j = 0; j < 32; ++j) { s += g_lnpart[j][tid][0]; s2 += g_lnpart[j][tid][1]; }
        float m = s * (1.f / 512);
        smean[tid] = m;
        srstd[tid] = rsqrtf(s2 * (1.f / 512) - m * m + EPS);
    }
    __syncthreads();
    int c = tid & 7, r0 = (tid >> 3) * 2;
    float acc0 = 0.f, acc1 = 0.f;
    for (int kt = 0; kt < 512; kt += 32) {
        __syncthreads();
#pragma unroll
        for (int i = 0; i < 2; ++i) {
            int idx = tid + i * 256, rr = idx >> 3, k4 = (idx & 7) * 4;
            float4 hv = *(const float4*)&g_h[nx][rr][kt + k4];
            float4 gv = *(const float4*)&lnhg[kt + k4];
            float4 bv = *(const float4*)&lnhb[kt + k4];
            float m = smean[rr], rs = srstd[rr];
            As[(k4 + 0) * 68 + rr] = (hv.x - m) * rs * gv.x + bv.x;
            As[(k4 + 1) * 68 + rr] = (hv.y - m) * rs * gv.y + bv.y;
            As[(k4 + 2) * 68 + rr] = (hv.z - m) * rs * gv.z + bv.z;
            As[(k4 + 3) * 68 + rr] = (hv.w - m) * rs * gv.w + bv.w;
        }
        if (tid < 64) {
            int cc = tid >> 3, k4 = (tid & 7) * 4;
            const float* wp = headrow(q * 8 + cc, Wrk, Wwk, Wws, Wer, Wad);
            float4 v = wp ? *(const float4*)(wp + kt + k4) : make_float4(0.f, 0.f, 0.f, 0.f);
            Ws[(k4 + 0) * 12 + cc] = v.x; Ws[(k4 + 1) * 12 + cc] = v.y;
            Ws[(k4 + 2) * 12 + cc] = v.z; Ws[(k4 + 3) * 12 + cc] = v.w;
        }
        __syncthreads();
#pragma unroll
        for (int k = 0; k < 32; ++k) {
            float2 a = *(const float2*)&As[k * 68 + r0];
            float w = Ws[k * 12 + c];
            acc0 += a.x * w; acc1 += a.y * w;
        }
    }
    g_head[r0][q * 8 + c] = acc0;
    g_head[r0 + 1][q * 8 + c] = acc1;
}

__device__ void doMem(int t, int b, float* s_mem, float* scr, const float* __restrict__ x,
                      const float* __restrict__ brk, const float* __restrict__ bwk,
                      const float* __restrict__ bws, const float* __restrict__ ber,
                      const float* __restrict__ bad,
                      const float* __restrict__ lnhg, const float* __restrict__ lnhb,
                      const float* __restrict__ lnrkg, const float* __restrict__ lnrkb,
                      const float* __restrict__ lnwkg, const float* __restrict__ lnwkb,
                      const float* __restrict__ lnmg, const float* __restrict__ lnmb,
                      const float* __restrict__ lnog, const float* __restrict__ lnob,
                      const float* __restrict__ lning, const float* __restrict__ lninb) {
    float* s_hn = scr;           // 512
    float* s_rk = scr + 512;     // 256
    float* s_wk = scr + 768;     // 64
    float* s_er = scr + 832;     // 64
    float* s_ad = scr + 896;     // 64
    float* s_wkln = scr + 960;   // 64
    float* s_rkln = scr + 1024;  // 256
    float* s_wsc = scr + 1280;   // 256
    float* s_rsc = scr + 1536;   // 1024
    float* s_rv = scr + 2560;    // 256
    float* red = scr + 2816;     // 8
    float* misc = scr + 2824;    // 4
    int tid = threadIdx.x, warp = tid >> 5, lane = tid & 31;
    int nx = (t + 1) & 1;

    if (tid < 32) {
        float s = g_lnpart[tid][b][0], s2 = g_lnpart[tid][b][1];
#pragma unroll
        for (int o = 16; o; o >>= 1) {
            s += __shfl_xor_sync(0xffffffffu, s, o);
            s2 += __shfl_xor_sync(0xffffffffu, s2, o);
        }
        if (tid == 0) {
            float m = s * (1.f / 512);
            misc[1] = m;
            misc[2] = rsqrtf(s2 * (1.f / 512) - m * m + EPS);
        }
    }
    __syncthreads();
    float hm = misc[1], hrs = misc[2];
#pragma unroll
    for (int u = 0; u < 2; ++u) {
        int k = tid + u * 256;
        s_hn[k] = (g_h[nx][b][k] - hm) * hrs * lnhg[k] + lnhb[k];
    }
    for (int j = tid; j < 449; j += 256) {
        float v = g_head[b][j];
        if (j < 256) s_rk[j] = v + brk[j];
        else if (j < 320) s_wk[j - 256] = v + bwk[j - 256];
        else if (j == 320) misc[0] = sigf(v + bws[0]);
        else if (j < 385) s_er[j - 321] = sigf(v + ber[j - 321]);
        else s_ad[j - 385] = tanhf(v + bad[j - 385]);
    }
    __syncthreads();
    if (warp == 0) {
        float x0 = s_wk[lane], x1 = s_wk[lane + 32], s = x0 + x1;
#pragma unroll
        for (int o = 16; o; o >>= 1) s += __shfl_xor_sync(0xffffffffu, s, o);
        float mean = s * (1.f / 64), d0 = x0 - mean, d1 = x1 - mean;
        float vs = d0 * d0 + d1 * d1;
#pragma unroll
        for (int o = 16; o; o >>= 1) vs += __shfl_xor_sync(0xffffffffu, vs, o);
        float rs = rsqrtf(vs * (1.f / 64) + EPS);
        s_wkln[lane] = d0 * rs * lnwkg[lane] + lnwkb[lane];
        s_wkln[lane + 32] = d1 * rs * lnwkg[lane + 32] + lnwkb[lane + 32];
    } else if (warp <= 4) {
        int r = warp - 1;
        float x0 = s_rk[r * 64 + lane], x1 = s_rk[r * 64 + lane + 32], s = x0 + x1;
#pragma unroll
        for (int o = 16; o; o >>= 1) s += __shfl_xor_sync(0xffffffffu, s, o);
        float mean = s * (1.f / 64), d0 = x0 - mean, d1 = x1 - mean;
        float vs = d0 * d0 + d1 * d1;
#pragma unroll
        for (int o = 16; o; o >>= 1) vs += __shfl_xor_sync(0xffffffffu, vs, o);
        float rs = rsqrtf(vs * (1.f / 64) + EPS);
        s_rkln[r * 64 + lane] = d0 * rs * lnrkg[lane] + lnrkb[lane];
        s_rkln[r * 64 + lane + 32] = d1 * rs * lnrkg[lane + 32] + lnrkb[lane + 32];
    }
    __syncthreads();
    float mg0 = lnmg[lane], mg1 = lnmg[lane + 32];
    float mb0 = lnmb[lane], mb1 = lnmb[lane + 32];
    float wkl0 = s_wkln[lane], wkl1 = s_wkln[lane + 32];
    for (int m = warp; m < cM; m += 8) {
        float x0 = s_mem[m * 64 + lane], x1 = s_mem[m * 64 + lane + 32], s = x0 + x1;
#pragma unroll
        for (int o = 16; o; o >>= 1) s += __shfl_xor_sync(0xffffffffu, s, o);
        float mean = s * (1.f / 64), d0 = x0 - mean, d1 = x1 - mean;
        float vs = d0 * d0 + d1 * d1;
#pragma unroll
        for (int o = 16; o; o >>= 1) vs += __shfl_xor_sync(0xffffffffu, vs, o);
        float rs = rsqrtf(vs * (1.f / 64) + EPS);
        float dot = (d0 * rs * mg0 + mb0) * wkl0 + (d1 * rs * mg1 + mb1) * wkl1;
#pragma unroll
        for (int o = 16; o; o >>= 1) dot += __shfl_xor_sync(0xffffffffu, dot, o);
        if (lane == 0) s_wsc[m] = dot;
    }
    __syncthreads();
    {
        float v = s_wsc[tid];
        float mx = brmax(v, red);
        float e = expf(v - mx);
        float su = brsum(e, red);
        s_wsc[tid] = e / su * misc[0];
    }
    __syncthreads();
    for (int i = tid; i < cM * cHD; i += 256) {
        int m = i >> 6, hh = i & 63;
        float w = s_wsc[m];
        s_mem[i] = s_mem[i] * (1.f - w * s_er[hh]) + w * s_ad[hh];
    }
    __syncthreads();
    for (int m = warp; m < cM; m += 8) {
        float x0 = s_mem[m * 64 + lane], x1 = s_mem[m * 64 + lane + 32], s = x0 + x1;
#pragma unroll
        for (int o = 16; o; o >>= 1) s += __shfl_xor_sync(0xffffffffu, s, o);
        float mean = s * (1.f / 64), d0 = x0 - mean, d1 = x1 - mean;
        float vs = d0 * d0 + d1 * d1;
#pragma unroll
        for (int o = 16; o; o >>= 1) vs += __shfl_xor_sync(0xffffffffu, vs, o);
        float rs = rsqrtf(vs * (1.f / 64) + EPS);
        float n0 = d0 * rs * mg0 + mb0, n1 = d1 * rs * mg1 + mb1;
#pragma unroll
        for (int r = 0; r < 4; ++r) {
            float a = n0 * s_rkln[r * 64 + lane] + n1 * s_rkln[r * 64 + lane + 32];
#pragma unroll
            for (int o = 16; o; o >>= 1) a += __shfl_xor_sync(0xffffffffu, a, o);
            if (lane == 0) s_rsc[r * 256 + m] = a;
        }
    }
    __syncthreads();
#pragma unroll
    for (int r = 0; r < 4; ++r) {
        float v = s_rsc[r * 256 + tid];
        float mx = brmax(v, red);
        float e = expf(v - mx);
        float su = brsum(e, red);
        s_rsc[r * 256 + tid] = e / su;
    }
    __syncthreads();
    {
        int r = tid >> 6, hh = tid & 63;
        float acc = 0.f;
        for (int m = 0; m < cM; ++m) acc += s_rsc[r * 256 + m] * s_mem[m * 64 + hh];
        s_rv[tid] = acc;
    }
    __syncthreads();
    {
        float o0 = s_hn[tid], o1 = s_hn[tid + 256], o2 = s_rv[tid];
        float mean = brsum(o0 + o1 + o2, red) * (1.f / cTO);
        float d0 = o0 - mean, d1 = o1 - mean, d2 = o2 - mean;
        float var = brsum(d0 * d0 + d1 * d1 + d2 * d2, red) * (1.f / cTO);
        float rs = rsqrtf(var + EPS);
        g_outln[b][tid] = d0 * rs * lnog[tid] + lnob[tid];
        g_outln[b][tid + 256] = d1 * rs * lnog[tid + 256] + lnob[tid + 256];
        g_outln[b][tid + 512] = d2 * rs * lnog[tid + 512] + lnob[tid + 512];
    }
    if (t + 1 < cL) {
        const float* xn = x + ((size_t)b * cL + t + 1) * cE;
        float a0 = xn[tid], a1 = s_rv[tid];
        float mean = brsum(a0 + a1, red) * (1.f / cCI);
        float d0 = a0 - mean, d1 = a1 - mean;
        float var = brsum(d0 * d0 + d1 * d1, red) * (1.f / cCI);
        float rs = rsqrtf(var + EPS);
        g_ci[b][tid] = d0 * rs * lning[tid] + lninb[tid];
        g_ci[b][tid + 256] = d1 * rs * lning[tid + 256] + lninb[tid + 256];
    }
}

__global__ void __launch_bounds__(256, 1) k_persist(
    const float* __restrict__ x, const float* __restrict__ Wih,
    const float* __restrict__ Whh, const float* __restrict__ bih,
    const float* __restrict__ bhh, const float* __restrict__ lning,
    const float* __restrict__ lninb, const float* __restrict__ lnhg,
    const float* __restrict__ lnhb, const float* __restrict__ Wrk,
    const float* __restrict__ brk, const float* __restrict__ Wwk,
    const float* __restrict__ bwk, const float* __restrict__ Wws,
    const float* __restrict__ bws, const float* __restrict__ Wer,
    const float* __restrict__ ber, const float* __restrict__ Wad,
    const float* __restrict__ bad, const float* __restrict__ lnrkg,
    const float* __restrict__ lnrkb, const float* __restrict__ lnwkg,
    const float* __restrict__ lnwkb, const float* __restrict__ lnmg,
    const float* __restrict__ lnmb, const float* __restrict__ lnog,
    const float* __restrict__ lnob, const float* __restrict__ Wproj,
    const float* __restrict__ bproj, float* __restrict__ out,
    float* __restrict__ memg, float* __restrict__ hout, float* __restrict__ cout) {
    extern __shared__ float sm[];
    float* s_mem = sm;          // 16384 (persistent per-batch memory, blocks 0..63)
    float* scr = sm + 16384;    // 4096 scratch
    int bx = blockIdx.x, tid = threadIdx.x;

    // init: zero state; ci0 = LN([x_0, 0])
    if (bx < 64) {
        for (int i = tid; i < cM * cHD; i += 256) s_mem[i] = 0.f;
        int b = bx;
#pragma unroll
        for (int u = 0; u < 2; ++u) {
            int k = tid + u * 256;
            g_c[b][k] = 0.f;
            g_h[0][b][k] = 0.f;
        }
        float* red = scr;
        float a0 = x[(size_t)b * cL * cE + tid];
        float mean = brsum(a0, red) * (1.f / cCI);
        float d0 = a0 - mean, d1 = -mean;
        float var = brsum(d0 * d0 + d1 * d1, red) * (1.f / cCI);
        float rs = rsqrtf(var + EPS);
        g_ci[b][tid] = d0 * rs * lning[tid] + lninb[tid];
        g_ci[b][tid + 256] = d1 * rs * lning[tid + 256] + lninb[tid + 256];
    }
    gsync();

    for (int t = 0; t < cL; ++t) {
        doA(t, scr, Wih, Whh, bih, bhh);
        gsync();
        if (bx < 64) {
            if (t > 0) doProj(bx, t - 1, scr, Wproj, bproj, out);
        } else {
            doHeads(bx - 64, (t + 1) & 1, scr, lnhg, lnhb, Wrk, Wwk, Wws, Wer, Wad);
        }
        gsync();
        if (bx < 64)
            doMem(t, bx, s_mem, scr, x, brk, bwk, bws, ber, bad, lnhg, lnhb,
                  lnrkg, lnrkb, lnwkg, lnwkb, lnmg, lnmb, lnog, lnob, lning, lninb);
        gsync();
    }
    // final proj (t=255) + state/memory writeback
    if (bx < 64) {
        doProj(bx, cL - 1, scr, Wproj, bproj, out);
        int b = bx;
        for (int i = tid; i < cM * cHD; i += 256) memg[(size_t)b * cM * cHD + i] = s_mem[i];
#pragma unroll
        for (int u = 0; u < 2; ++u) {
            int k = tid + u * 256;
            hout[b * cH + k] = g_h[0][b][k];
            cout[b * cH + k] = g_c[b][k];
        }
    }
}

extern "C" void kernel_launch(void* const* d_in, const int* in_sizes, int n_in,
                              void* d_out, int out_size) {
    const float** p = (const float**)d_in;
    float* out = (float*)d_out;
    float* memg = out + (size_t)cB * cL * cO;
    float* hout = memg + (size_t)cB * cM * cHD;
    float* cout = hout + (size_t)cB * cH;
    const int smem = (16384 + 4096) * 4;
    cudaFuncSetAttribute(k_persist, cudaFuncAttributeMaxDynamicSharedMemorySize, smem);
    k_persist<<<NBLK, 256, smem>>>(p[0], p[1], p[2], p[3], p[4], p[5], p[6], p[7], p[8],
                                   p[9], p[10], p[11], p[12], p[13], p[14], p[15], p[16],
                                   p[17], p[18], p[19], p[20], p[21], p[22], p[23], p[24],
                                   p[25], p[26], p[27], p[28], out, memg, hout, cout);
}

// round 10
// speedup vs baseline: 1.1456x; 1.1456x over previous
#include <cuda_runtime.h>
#include <math.h>

#define cB 64
#define cL 256
#define cE 256
#define cH 512
#define cM 256
#define cHD 64
#define cO 1024
#define cCI 512
#define cTO 768
#define EPS 1e-5f
#define NBLK 128

typedef unsigned long long ull;

__device__ float g_h[2][cB][cH];
__device__ float g_c[cB][cH];
__device__ float g_ci[cB][cCI];
__device__ float g_outln[2][cB][cTO];
__device__ float g_head[cB][512];
__device__ float g_lnpart[128][cB][2];
__device__ unsigned g_cnt = 0;
__device__ unsigned g_gen = 0;

__device__ __forceinline__ float sigf(float x) { return 1.0f / (1.0f + expf(-x)); }

__device__ __forceinline__ ull dup2(float w) {
    ull r;
    asm("mov.b64 %0, {%1, %1};" : "=l"(r) : "f"(w));
    return r;
}
__device__ __forceinline__ void ffma2(ull& acc, ull a, ull b) {
    asm("fma.rn.f32x2 %0, %1, %2, %0;" : "+l"(acc) : "l"(a), "l"(b));
}
__device__ __forceinline__ float2 unpk(ull v) {
    float2 r;
    asm("mov.b64 {%0, %1}, %2;" : "=f"(r.x), "=f"(r.y) : "l"(v));
    return r;
}

__device__ __forceinline__ void gsync() {
    __syncthreads();
    if (threadIdx.x == 0) {
        unsigned gen = *(volatile unsigned*)&g_gen;
        __threadfence();
        if (atomicAdd(&g_cnt, 1u) == NBLK - 1) {
            g_cnt = 0;
            __threadfence();
            *(volatile unsigned*)&g_gen = gen + 1;
        } else {
            while (*(volatile unsigned*)&g_gen == gen) {}
        }
        __threadfence();
    }
    __syncthreads();
}

__device__ __forceinline__ float brsum(float v, float* red) {
    int tid = threadIdx.x;
#pragma unroll
    for (int o = 16; o; o >>= 1) v += __shfl_xor_sync(0xffffffffu, v, o);
    if ((tid & 31) == 0) red[tid >> 5] = v;
    __syncthreads();
    if (tid == 0) { float s = 0.f; for (int i = 0; i < 8; ++i) s += red[i]; red[0] = s; }
    __syncthreads();
    float r = red[0];
    __syncthreads();
    return r;
}
__device__ __forceinline__ float brmax(float v, float* red) {
    int tid = threadIdx.x;
#pragma unroll
    for (int o = 16; o; o >>= 1) v = fmaxf(v, __shfl_xor_sync(0xffffffffu, v, o));
    if ((tid & 31) == 0) red[tid >> 5] = v;
    __syncthreads();
    if (tid == 0) { float s = red[0]; for (int i = 1; i < 8; ++i) s = fmaxf(s, red[i]); red[0] = s; }
    __syncthreads();
    float r = red[0];
    __syncthreads();
    return r;
}

__device__ __forceinline__ const float* headrow(int g, const float* Wrk, const float* Wwk,
                                                const float* Wws, const float* Wer,
                                                const float* Wad) {
    if (g < 256) return Wrk + (size_t)g * 512;
    if (g < 320) return Wwk + (size_t)(g - 256) * 512;
    if (g == 320) return Wws;
    if (g < 385) return Wer + (size_t)(g - 321) * 512;
    if (g < 449) return Wad + (size_t)(g - 385) * 512;
    return nullptr;
}

// phase A: gates GEMM [64 x 16cols, K=1024] via f32x2 + fused LSTM (4 units/block)
__device__ void doA(int t, float* scr, const float* __restrict__ Wih,
                    const float* __restrict__ Whh, const float* __restrict__ bih,
                    const float* __restrict__ bhh) {
    int tid = threadIdx.x, jj = blockIdx.x;
    int u0 = jj * 4, cur = t & 1, nx = (t + 1) & 1;
    float* As = scr;          // [32][66] k-major, 64 batches
    float* Ws = scr + 2112;   // [32][16] k-major, 16 cols
    int mt = tid >> 3, nt = tid & 7;  // m-pair, n-pair
    ull acc0 = 0ull, acc1 = 0ull;
    for (int kt = 0; kt < 1024; kt += 32) {
        __syncthreads();
#pragma unroll
        for (int i = 0; i < 2; ++i) {
            int idx = tid + i * 256, m = idx >> 3, kq = (idx & 7) * 4;
            const float* src = (kt < 512) ? &g_ci[m][kt + kq] : &g_h[cur][m][kt - 512 + kq];
            float4 v = *(const float4*)src;
            As[(kq + 0) * 66 + m] = v.x; As[(kq + 1) * 66 + m] = v.y;
            As[(kq + 2) * 66 + m] = v.z; As[(kq + 3) * 66 + m] = v.w;
        }
        if (tid < 128) {
            int c = tid >> 3, kq = (tid & 7) * 4;
            int row = (c >> 2) * 512 + u0 + (c & 3);
            const float* ws = (kt < 512) ? Wih + (size_t)row * 512 + kt + kq
                                         : Whh + (size_t)row * 512 + (kt - 512) + kq;
            float4 v = *(const float4*)ws;
            Ws[(kq + 0) * 16 + c] = v.x; Ws[(kq + 1) * 16 + c] = v.y;
            Ws[(kq + 2) * 16 + c] = v.z; Ws[(kq + 3) * 16 + c] = v.w;
        }
        __syncthreads();
#pragma unroll
        for (int k = 0; k < 32; ++k) {
            ull a = *(const ull*)&As[k * 66 + mt * 2];
            float2 w = *(const float2*)&Ws[k * 16 + nt * 2];
            ffma2(acc0, a, dup2(w.x));
            ffma2(acc1, a, dup2(w.y));
        }
    }
    __syncthreads();
    float* Cs = scr;          // [16][66]
    float* Ps = scr + 2700;   // 256
    {
        float2 r0 = unpk(acc0), r1 = unpk(acc1);
        Cs[(2 * nt) * 66 + 2 * mt] = r0.x; Cs[(2 * nt) * 66 + 2 * mt + 1] = r0.y;
        Cs[(2 * nt + 1) * 66 + 2 * mt] = r1.x; Cs[(2 * nt + 1) * 66 + 2 * mt + 1] = r1.y;
    }
    __syncthreads();
    int m = tid & 63, u = tid >> 6;
    int U = u0 + u;
    float gi = Cs[(u) * 66 + m]      + bih[U]        + bhh[U];
    float gf = Cs[(4 + u) * 66 + m]  + bih[512 + U]  + bhh[512 + U];
    float gg = Cs[(8 + u) * 66 + m]  + bih[1024 + U] + bhh[1024 + U];
    float go = Cs[(12 + u) * 66 + m] + bih[1536 + U] + bhh[1536 + U];
    float cc = sigf(gf) * g_c[m][U] + sigf(gi) * tanhf(gg);
    float hh = sigf(go) * tanhf(cc);
    g_c[m][U] = cc;
    g_h[nx][m][U] = hh;
    Ps[u * 64 + m] = hh;
    __syncthreads();
    if (tid < 64) {
        float h0 = Ps[tid], h1 = Ps[64 + tid], h2 = Ps[128 + tid], h3 = Ps[192 + tid];
        g_lnpart[jj][tid][0] = h0 + h1 + h2 + h3;
        g_lnpart[jj][tid][1] = h0 * h0 + h1 * h1 + h2 * h2 + h3 * h3;
    }
}

// phase B: heads GEMM, 4 cols per block (128 blocks), LN(h) inline
__device__ void doHeads(int q, int nx, float* scr,
                        const float* __restrict__ lnhg, const float* __restrict__ lnhb,
                        const float* __restrict__ Wrk, const float* __restrict__ Wwk,
                        const float* __restrict__ Wws, const float* __restrict__ Wer,
                        const float* __restrict__ Wad) {
    int tid = threadIdx.x;
    float* As = scr;           // [32][66]
    float* Ws = scr + 2112;    // [32][4]
    float* smean = scr + 2304; // 64
    float* srstd = scr + 2368; // 64
    if (tid < 64) {
        float s = 0.f, s2 = 0.f;
        for (int j = 0; j < 128; ++j) { s += g_lnpart[j][tid][0]; s2 += g_lnpart[j][tid][1]; }
        float m = s * (1.f / 512);
        smean[tid] = m;
        srstd[tid] = rsqrtf(s2 * (1.f / 512) - m * m + EPS);
    }
    __syncthreads();
    int m = tid >> 2, c = tid & 3;
    float acc = 0.f;
    for (int kt = 0; kt < 512; kt += 32) {
        __syncthreads();
#pragma unroll
        for (int i = 0; i < 2; ++i) {
            int idx = tid + i * 256, r = idx >> 3, kq = (idx & 7) * 4;
            float4 hv = *(const float4*)&g_h[nx][r][kt + kq];
            float4 gv = *(const float4*)&lnhg[kt + kq];
            float4 bv = *(const float4*)&lnhb[kt + kq];
            float mm = smean[r], rs = srstd[r];
            As[(kq + 0) * 66 + r] = (hv.x - mm) * rs * gv.x + bv.x;
            As[(kq + 1) * 66 + r] = (hv.y - mm) * rs * gv.y + bv.y;
            As[(kq + 2) * 66 + r] = (hv.z - mm) * rs * gv.z + bv.z;
            As[(kq + 3) * 66 + r] = (hv.w - mm) * rs * gv.w + bv.w;
        }
        if (tid < 32) {
            int c2 = tid >> 3, kq = (tid & 7) * 4;
            const float* wp = headrow(q * 4 + c2, Wrk, Wwk, Wws, Wer, Wad);
            float4 v = wp ? *(const float4*)(wp + kt + kq) : make_float4(0.f, 0.f, 0.f, 0.f);
            Ws[(kq + 0) * 4 + c2] = v.x; Ws[(kq + 1) * 4 + c2] = v.y;
            Ws[(kq + 2) * 4 + c2] = v.z; Ws[(kq + 3) * 4 + c2] = v.w;
        }
        __syncthreads();
#pragma unroll
        for (int k = 0; k < 32; ++k) acc += As[k * 66 + m] * Ws[k * 4 + c];
    }
    g_head[m][q * 4 + c] = acc;
}

// phase C (blocks 64..127): proj, 16 cols per block, K=768
__device__ void doProj(int p, int trow, float* scr, const float* __restrict__ Aouts,
                       const float* __restrict__ Wproj, const float* __restrict__ bproj,
                       float* __restrict__ out) {
    int tid = threadIdx.x;
    float* As = scr;          // [32][68]
    float* Ws = scr + 2176;   // [32][20]
    int r0 = (tid >> 3) * 2, c0 = (tid & 7) * 2;
    float a00 = 0.f, a01 = 0.f, a10 = 0.f, a11 = 0.f;
    for (int kt = 0; kt < 768; kt += 32) {
        __syncthreads();
#pragma unroll
        for (int i = 0; i < 2; ++i) {
            int idx = tid + i * 256, rr = idx >> 3, k4 = (idx & 7) * 4;
            float4 v = *(const float4*)&Aouts[rr * 768 + kt + k4];
            As[(k4 + 0) * 68 + rr] = v.x; As[(k4 + 1) * 68 + rr] = v.y;
            As[(k4 + 2) * 68 + rr] = v.z; As[(k4 + 3) * 68 + rr] = v.w;
        }
        if (tid < 128) {
            int cc = tid >> 3, k4 = (tid & 7) * 4;
            float4 v = *(const float4*)&Wproj[(size_t)(16 * p + cc) * 768 + kt + k4];
            Ws[(k4 + 0) * 20 + cc] = v.x; Ws[(k4 + 1) * 20 + cc] = v.y;
            Ws[(k4 + 2) * 20 + cc] = v.z; Ws[(k4 + 3) * 20 + cc] = v.w;
        }
        __syncthreads();
#pragma unroll
        for (int k = 0; k < 32; ++k) {
            float2 a = *(const float2*)&As[k * 68 + r0];
            float2 w = *(const float2*)&Ws[k * 20 + c0];
            a00 += a.x * w.x; a01 += a.x * w.y; a10 += a.y * w.x; a11 += a.y * w.y;
        }
    }
    int col = 16 * p + c0;
    float b0 = bproj[col], b1 = bproj[col + 1];
    out[((size_t)(r0 + 0) * cL + trow) * cO + col]     = a00 + b0;
    out[((size_t)(r0 + 0) * cL + trow) * cO + col + 1] = a01 + b1;
    out[((size_t)(r0 + 1) * cL + trow) * cO + col]     = a10 + b0;
    out[((size_t)(r0 + 1) * cL + trow) * cO + col + 1] = a11 + b1;
}

// phase C (blocks 0..63): memory write/read + outln + next ci
__device__ void doMem(int t, int b, float* s_mem, float* scr, const float* __restrict__ x,
                      const float* __restrict__ brk, const float* __restrict__ bwk,
                      const float* __restrict__ bws, const float* __restrict__ ber,
                      const float* __restrict__ bad,
                      const float* __restrict__ lnhg, const float* __restrict__ lnhb,
                      const float* __restrict__ lnrkg, const float* __restrict__ lnrkb,
                      const float* __restrict__ lnwkg, const float* __restrict__ lnwkb,
                      const float* __restrict__ lnmg, const float* __restrict__ lnmb,
                      const float* __restrict__ lnog, const float* __restrict__ lnob,
                      const float* __restrict__ lning, const float* __restrict__ lninb) {
    float* s_hn = scr;           // 512
    float* s_rk = scr + 512;     // 256
    float* s_wk = scr + 768;     // 64
    float* s_er = scr + 832;     // 64
    float* s_ad = scr + 896;     // 64
    float* s_wkln = scr + 960;   // 64
    float* s_rkln = scr + 1024;  // 256
    float* s_wsc = scr + 1280;   // 256
    float* s_rsc = scr + 1536;   // 1024
    float* s_rv = scr + 2560;    // 256
    float* red = scr + 2816;     // 8
    float* misc = scr + 2824;    // 4
    int tid = threadIdx.x, warp = tid >> 5, lane = tid & 31;
    int nx = (t + 1) & 1, ob = t & 1;

    if (tid < 32) {
        float s = 0.f, s2 = 0.f;
#pragma unroll
        for (int j = 0; j < 4; ++j) {
            s += g_lnpart[lane * 4 + j][b][0];
            s2 += g_lnpart[lane * 4 + j][b][1];
        }
#pragma unroll
        for (int o = 16; o; o >>= 1) {
            s += __shfl_xor_sync(0xffffffffu, s, o);
            s2 += __shfl_xor_sync(0xffffffffu, s2, o);
        }
        if (tid == 0) {
            float m = s * (1.f / 512);
            misc[1] = m;
            misc[2] = rsqrtf(s2 * (1.f / 512) - m * m + EPS);
        }
    }
    __syncthreads();
    float hm = misc[1], hrs = misc[2];
#pragma unroll
    for (int u = 0; u < 2; ++u) {
        int k = tid + u * 256;
        s_hn[k] = (g_h[nx][b][k] - hm) * hrs * lnhg[k] + lnhb[k];
    }
    for (int j = tid; j < 449; j += 256) {
        float v = g_head[b][j];
        if (j < 256) s_rk[j] = v + brk[j];
        else if (j < 320) s_wk[j - 256] = v + bwk[j - 256];
        else if (j == 320) misc[0] = sigf(v + bws[0]);
        else if (j < 385) s_er[j - 321] = sigf(v + ber[j - 321]);
        else s_ad[j - 385] = tanhf(v + bad[j - 385]);
    }
    __syncthreads();
    if (warp == 0) {
        float x0 = s_wk[lane], x1 = s_wk[lane + 32], s = x0 + x1;
#pragma unroll
        for (int o = 16; o; o >>= 1) s += __shfl_xor_sync(0xffffffffu, s, o);
        float mean = s * (1.f / 64), d0 = x0 - mean, d1 = x1 - mean;
        float vs = d0 * d0 + d1 * d1;
#pragma unroll
        for (int o = 16; o; o >>= 1) vs += __shfl_xor_sync(0xffffffffu, vs, o);
        float rs = rsqrtf(vs * (1.f / 64) + EPS);
        s_wkln[lane] = d0 * rs * lnwkg[lane] + lnwkb[lane];
        s_wkln[lane + 32] = d1 * rs * lnwkg[lane + 32] + lnwkb[lane + 32];
    } else if (warp <= 4) {
        int r = warp - 1;
        float x0 = s_rk[r * 64 + lane], x1 = s_rk[r * 64 + lane + 32], s = x0 + x1;
#pragma unroll
        for (int o = 16; o; o >>= 1) s += __shfl_xor_sync(0xffffffffu, s, o);
        float mean = s * (1.f / 64), d0 = x0 - mean, d1 = x1 - mean;
        float vs = d0 * d0 + d1 * d1;
#pragma unroll
        for (int o = 16; o; o >>= 1) vs += __shfl_xor_sync(0xffffffffu, vs, o);
        float rs = rsqrtf(vs * (1.f / 64) + EPS);
        s_rkln[r * 64 + lane] = d0 * rs * lnrkg[lane] + lnrkb[lane];
        s_rkln[r * 64 + lane + 32] = d1 * rs * lnrkg[lane + 32] + lnrkb[lane + 32];
    }
    __syncthreads();
    float mg0 = lnmg[lane], mg1 = lnmg[lane + 32];
    float mb0 = lnmb[lane], mb1 = lnmb[lane + 32];
    float wkl0 = s_wkln[lane], wkl1 = s_wkln[lane + 32];
    for (int m = warp; m < cM; m += 8) {
        float x0 = s_mem[m * 64 + lane], x1 = s_mem[m * 64 + lane + 32], s = x0 + x1;
#pragma unroll
        for (int o = 16; o; o >>= 1) s += __shfl_xor_sync(0xffffffffu, s, o);
        float mean = s * (1.f / 64), d0 = x0 - mean, d1 = x1 - mean;
        float vs = d0 * d0 + d1 * d1;
#pragma unroll
        for (int o = 16; o; o >>= 1) vs += __shfl_xor_sync(0xffffffffu, vs, o);
        float rs = rsqrtf(vs * (1.f / 64) + EPS);
        float dot = (d0 * rs * mg0 + mb0) * wkl0 + (d1 * rs * mg1 + mb1) * wkl1;
#pragma unroll
        for (int o = 16; o; o >>= 1) dot += __shfl_xor_sync(0xffffffffu, dot, o);
        if (lane == 0) s_wsc[m] = dot;
    }
    __syncthreads();
    {
        float v = s_wsc[tid];
        float mx = brmax(v, red);
        float e = expf(v - mx);
        float su = brsum(e, red);
        s_wsc[tid] = e / su * misc[0];
    }
    __syncthreads();
    for (int i = tid; i < cM * cHD; i += 256) {
        int m = i >> 6, hh = i & 63;
        float w = s_wsc[m];
        s_mem[i] = s_mem[i] * (1.f - w * s_er[hh]) + w * s_ad[hh];
    }
    __syncthreads();
    for (int m = warp; m < cM; m += 8) {
        float x0 = s_mem[m * 64 + lane], x1 = s_mem[m * 64 + lane + 32], s = x0 + x1;
#pragma unroll
        for (int o = 16; o; o >>= 1) s += __shfl_xor_sync(0xffffffffu, s, o);
        float mean = s * (1.f / 64), d0 = x0 - mean, d1 = x1 - mean;
        float vs = d0 * d0 + d1 * d1;
#pragma unroll
        for (int o = 16; o; o >>= 1) vs += __shfl_xor_sync(0xffffffffu, vs, o);
        float rs = rsqrtf(vs * (1.f / 64) + EPS);
        float n0 = d0 * rs * mg0 + mb0, n1 = d1 * rs * mg1 + mb1;
#pragma unroll
        for (int r = 0; r < 4; ++r) {
            float a = n0 * s_rkln[r * 64 + lane] + n1 * s_rkln[r * 64 + lane + 32];
#pragma unroll
            for (int o = 16; o; o >>= 1) a += __shfl_xor_sync(0xffffffffu, a, o);
            if (lane == 0) s_rsc[r * 256 + m] = a;
        }
    }
    __syncthreads();
#pragma unroll
    for (int r = 0; r < 4; ++r) {
        float v = s_rsc[r * 256 + tid];
        float mx = brmax(v, red);
        float e = expf(v - mx);
        float su = brsum(e, red);
        s_rsc[r * 256 + tid] = e / su;
    }
    __syncthreads();
    {
        int r = tid >> 6, hh = tid & 63;
        float acc = 0.f;
        for (int m = 0; m < cM; ++m) acc += s_rsc[r * 256 + m] * s_mem[m * 64 + hh];
        s_rv[tid] = acc;
    }
    __syncthreads();
    {
        float o0 = s_hn[tid], o1 = s_hn[tid + 256], o2 = s_rv[tid];
        float mean = brsum(o0 + o1 + o2, red) * (1.f / cTO);
        float d0 = o0 - mean, d1 = o1 - mean, d2 = o2 - mean;
        float var = brsum(d0 * d0 + d1 * d1 + d2 * d2, red) * (1.f / cTO);
        float rs = rsqrtf(var + EPS);
        g_outln[ob][b][tid] = d0 * rs * lnog[tid] + lnob[tid];
        g_outln[ob][b][tid + 256] = d1 * rs * lnog[tid + 256] + lnob[tid + 256];
        g_outln[ob][b][tid + 512] = d2 * rs * lnog[tid + 512] + lnob[tid + 512];
    }
    if (t + 1 < cL) {
        const float* xn = x + ((size_t)b * cL + t + 1) * cE;
        float a0 = xn[tid], a1 = s_rv[tid];
        float mean = brsum(a0 + a1, red) * (1.f / cCI);
        float d0 = a0 - mean, d1 = a1 - mean;
        float var = brsum(d0 * d0 + d1 * d1, red) * (1.f / cCI);
        float rs = rsqrtf(var + EPS);
        g_ci[b][tid] = d0 * rs * lning[tid] + lninb[tid];
        g_ci[b][tid + 256] = d1 * rs * lning[tid + 256] + lninb[tid + 256];
    }
}

__global__ void __launch_bounds__(256, 1) k_persist(
    const float* __restrict__ x, const float* __restrict__ Wih,
    const float* __restrict__ Whh, const float* __restrict__ bih,
    const float* __restrict__ bhh, const float* __restrict__ lning,
    const float* __restrict__ lninb, const float* __restrict__ lnhg,
    const float* __restrict__ lnhb, const float* __restrict__ Wrk,
    const float* __restrict__ brk, const float* __restrict__ Wwk,
    const float* __restrict__ bwk, const float* __restrict__ Wws,
    const float* __restrict__ bws, const float* __restrict__ Wer,
    const float* __restrict__ ber, const float* __restrict__ Wad,
    const float* __restrict__ bad, const float* __restrict__ lnrkg,
    const float* __restrict__ lnrkb, const float* __restrict__ lnwkg,
    const float* __restrict__ lnwkb, const float* __restrict__ lnmg,
    const float* __restrict__ lnmb, const float* __restrict__ lnog,
    const float* __restrict__ lnob, const float* __restrict__ Wproj,
    const float* __restrict__ bproj, float* __restrict__ out,
    float* __restrict__ memg, float* __restrict__ hout, float* __restrict__ cout) {
    extern __shared__ float sm[];
    float* s_mem = sm;          // 16384 (persistent memory, blocks 0..63)
    float* scr = sm + 16384;    // 4096 scratch
    int bx = blockIdx.x, tid = threadIdx.x;

    if (bx < 64) {
        for (int i = tid; i < cM * cHD; i += 256) s_mem[i] = 0.f;
        int b = bx;
#pragma unroll
        for (int u = 0; u < 2; ++u) {
            int k = tid + u * 256;
            g_c[b][k] = 0.f;
            g_h[0][b][k] = 0.f;
        }
        float* red = scr;
        float a0 = x[(size_t)b * cL * cE + tid];
        float mean = brsum(a0, red) * (1.f / cCI);
        float d0 = a0 - mean, d1 = -mean;
        float var = brsum(d0 * d0 + d1 * d1, red) * (1.f / cCI);
        float rs = rsqrtf(var + EPS);
        g_ci[b][tid] = d0 * rs * lning[tid] + lninb[tid];
        g_ci[b][tid + 256] = d1 * rs * lning[tid + 256] + lninb[tid + 256];
    }
    gsync();

    for (int t = 0; t < cL; ++t) {
        doA(t, scr, Wih, Whh, bih, bhh);
        gsync();
        doHeads(bx, (t + 1) & 1, scr, lnhg, lnhb, Wrk, Wwk, Wws, Wer, Wad);
        gsync();
        if (bx < 64) {
            doMem(t, bx, s_mem, scr, x, brk, bwk, bws, ber, bad, lnhg, lnhb,
                  lnrkg, lnrkb, lnwkg, lnwkb, lnmg, lnmb, lnog, lnob, lning, lninb);
        } else if (t > 0) {
            doProj(bx - 64, t - 1, scr, &g_outln[(t - 1) & 1][0][0], Wproj, bproj, out);
        }
        gsync();
    }
    if (bx >= 64) {
        doProj(bx - 64, cL - 1, scr, &g_outln[(cL - 1) & 1][0][0], Wproj, bproj, out);
    } else {
        int b = bx;
        for (int i = tid; i < cM * cHD; i += 256) memg[(size_t)b * cM * cHD + i] = s_mem[i];
#pragma unroll
        for (int u = 0; u < 2; ++u) {
            int k = tid + u * 256;
            hout[b * cH + k] = g_h[0][b][k];
            cout[b * cH + k] = g_c[b][k];
        }
    }
}

extern "C" void kernel_launch(void* const* d_in, const int* in_sizes, int n_in,
                              void* d_out, int out_size) {
    const float** p = (const float**)d_in;
    float* out = (float*)d_out;
    float* memg = out + (size_t)cB * cL * cO;
    float* hout = memg + (size_t)cB * cM * cHD;
    float* cout = hout + (size_t)cB * cH;
    const int smem = (16384 + 4096) * 4;
    cudaFuncSetAttribute(k_persist, cudaFuncAttributeMaxDynamicSharedMemorySize, smem);
    k_persist<<<NBLK, 256, smem>>>(p[0], p[1], p[2], p[3], p[4], p[5], p[6], p[7], p[8],
                                   p[9], p[10], p[11], p[12], p[13], p[14], p[15], p[16],
                                   p[17], p[18], p[19], p[20], p[21], p[22], p[23], p[24],
                                   p[25], p[26], p[27], p[28], out, memg, hout, cout);
}

// round 11
// speedup vs baseline: 1.3330x; 1.1636x over previous
#include <cuda_runtime.h>
#include <math.h>

#define cB 64
#define cL 256
#define cE 256
#define cH 512
#define cM 256
#define cHD 64
#define cO 1024
#define cCI 512
#define cTO 768
#define EPS 1e-5f
#define NBLK 128

typedef unsigned long long ull;

__device__ float g_h[2][cB][cH];
__device__ float g_c[cB][cH];
__device__ float g_ci[cB][cCI];
__device__ float g_outln[2][cB][cTO];
__device__ float g_head[cB][512];
__device__ float g_lnpart[128][cB][2];
__device__ unsigned g_cnt = 0;
__device__ unsigned g_gen = 0;

__device__ __forceinline__ float sigf(float x) { return 1.0f / (1.0f + expf(-x)); }

__device__ __forceinline__ ull dup2(float w) {
    ull r;
    asm("mov.b64 %0, {%1, %1};" : "=l"(r) : "f"(w));
    return r;
}
__device__ __forceinline__ void ffma2(ull& acc, ull a, ull b) {
    asm("fma.rn.f32x2 %0, %1, %2, %0;" : "+l"(acc) : "l"(a), "l"(b));
}
__device__ __forceinline__ float2 unpk(ull v) {
    float2 r;
    asm("mov.b64 {%0, %1}, %2;" : "=f"(r.x), "=f"(r.y) : "l"(v));
    return r;
}

__device__ __forceinline__ void gsync() {
    __syncthreads();
    if (threadIdx.x == 0) {
        unsigned gen = *(volatile unsigned*)&g_gen;
        __threadfence();
        if (atomicAdd(&g_cnt, 1u) == NBLK - 1) {
            g_cnt = 0;
            __threadfence();
            *(volatile unsigned*)&g_gen = gen + 1;
        } else {
            while (*(volatile unsigned*)&g_gen == gen) {}
        }
        __threadfence();
    }
    __syncthreads();
}

__device__ __forceinline__ float brsum(float v, float* red) {
    int tid = threadIdx.x;
#pragma unroll
    for (int o = 16; o; o >>= 1) v += __shfl_xor_sync(0xffffffffu, v, o);
    if ((tid & 31) == 0) red[tid >> 5] = v;
    __syncthreads();
    if (tid == 0) { float s = 0.f; for (int i = 0; i < 8; ++i) s += red[i]; red[0] = s; }
    __syncthreads();
    float r = red[0];
    __syncthreads();
    return r;
}
__device__ __forceinline__ float brmax(float v, float* red) {
    int tid = threadIdx.x;
#pragma unroll
    for (int o = 16; o; o >>= 1) v = fmaxf(v, __shfl_xor_sync(0xffffffffu, v, o));
    if ((tid & 31) == 0) red[tid >> 5] = v;
    __syncthreads();
    if (tid == 0) { float s = red[0]; for (int i = 1; i < 8; ++i) s = fmaxf(s, red[i]); red[0] = s; }
    __syncthreads();
    float r = red[0];
    __syncthreads();
    return r;
}

__device__ __forceinline__ const float* headrow(int g, const float* Wrk, const float* Wwk,
                                                const float* Wws, const float* Wer,
                                                const float* Wad) {
    if (g < 256) return Wrk + (size_t)g * 512;
    if (g < 320) return Wwk + (size_t)(g - 256) * 512;
    if (g == 320) return Wws;
    if (g < 385) return Wer + (size_t)(g - 321) * 512;
    if (g < 449) return Wad + (size_t)(g - 385) * 512;
    return nullptr;
}

// phase A: gates GEMM [64 x 16cols, K=1024] f32x2 + fused LSTM; register-prefetched fills
__device__ void doA(int t, float* scr, const float* __restrict__ Wih,
                    const float* __restrict__ Whh, const float* __restrict__ bih,
                    const float* __restrict__ bhh) {
    int tid = threadIdx.x, jj = blockIdx.x;
    int u0 = jj * 4, cur = t & 1, nx = (t + 1) & 1;
    float* As = scr;          // [32][66]
    float* Ws = scr + 2112;   // [32][16]
    int mt = tid >> 3, nt = tid & 7;
    int am0 = tid >> 3, ak = (tid & 7) * 4;  // staging A: rows am0, am0+32
    int am1 = am0 + 32;
    int wc = tid >> 3, wk = (tid & 7) * 4;   // staging W (tid<128)
    int wrow = (wc >> 2) * 512 + u0 + (wc & 3);
    ull acc0 = 0ull, acc1 = 0ull;
    float4 va0, va1, vw;
    vw = make_float4(0.f, 0.f, 0.f, 0.f);

#define LDA_CHUNK(kt_)                                                                        \
    {                                                                                         \
        const float* s0_ = ((kt_) < 512) ? &g_ci[am0][(kt_) + ak]                             \
                                         : &g_h[cur][am0][(kt_) - 512 + ak];                  \
        const float* s1_ = ((kt_) < 512) ? &g_ci[am1][(kt_) + ak]                             \
                                         : &g_h[cur][am1][(kt_) - 512 + ak];                  \
        va0 = *(const float4*)s0_;                                                            \
        va1 = *(const float4*)s1_;                                                            \
        if (tid < 128) {                                                                      \
            const float* ws_ = ((kt_) < 512)                                                  \
                                   ? Wih + (size_t)wrow * 512 + (kt_) + wk                    \
                                   : Whh + (size_t)wrow * 512 + ((kt_) - 512) + wk;           \
            vw = *(const float4*)ws_;                                                         \
        }                                                                                     \
    }

    LDA_CHUNK(0)
    for (int kt = 0; kt < 1024; kt += 32) {
        __syncthreads();
        As[(ak + 0) * 66 + am0] = va0.x; As[(ak + 1) * 66 + am0] = va0.y;
        As[(ak + 2) * 66 + am0] = va0.z; As[(ak + 3) * 66 + am0] = va0.w;
        As[(ak + 0) * 66 + am1] = va1.x; As[(ak + 1) * 66 + am1] = va1.y;
        As[(ak + 2) * 66 + am1] = va1.z; As[(ak + 3) * 66 + am1] = va1.w;
        if (tid < 128) {
            Ws[(wk + 0) * 16 + wc] = vw.x; Ws[(wk + 1) * 16 + wc] = vw.y;
            Ws[(wk + 2) * 16 + wc] = vw.z; Ws[(wk + 3) * 16 + wc] = vw.w;
        }
        if (kt + 32 < 1024) LDA_CHUNK(kt + 32)
        __syncthreads();
#pragma unroll
        for (int k = 0; k < 32; ++k) {
            ull a = *(const ull*)&As[k * 66 + mt * 2];
            float2 w = *(const float2*)&Ws[k * 16 + nt * 2];
            ffma2(acc0, a, dup2(w.x));
            ffma2(acc1, a, dup2(w.y));
        }
    }
#undef LDA_CHUNK
    __syncthreads();
    float* Cs = scr;          // [16][66]
    float* Ps = scr + 2700;   // 256
    {
        float2 r0 = unpk(acc0), r1 = unpk(acc1);
        Cs[(2 * nt) * 66 + 2 * mt] = r0.x; Cs[(2 * nt) * 66 + 2 * mt + 1] = r0.y;
        Cs[(2 * nt + 1) * 66 + 2 * mt] = r1.x; Cs[(2 * nt + 1) * 66 + 2 * mt + 1] = r1.y;
    }
    __syncthreads();
    int m = tid & 63, u = tid >> 6;
    int U = u0 + u;
    float gi = Cs[(u) * 66 + m]      + bih[U]        + bhh[U];
    float gf = Cs[(4 + u) * 66 + m]  + bih[512 + U]  + bhh[512 + U];
    float gg = Cs[(8 + u) * 66 + m]  + bih[1024 + U] + bhh[1024 + U];
    float go = Cs[(12 + u) * 66 + m] + bih[1536 + U] + bhh[1536 + U];
    float cc = sigf(gf) * g_c[m][U] + sigf(gi) * tanhf(gg);
    float hh = sigf(go) * tanhf(cc);
    g_c[m][U] = cc;
    g_h[nx][m][U] = hh;
    Ps[u * 64 + m] = hh;
    __syncthreads();
    if (tid < 64) {
        float h0 = Ps[tid], h1 = Ps[64 + tid], h2 = Ps[128 + tid], h3 = Ps[192 + tid];
        g_lnpart[jj][tid][0] = h0 + h1 + h2 + h3;
        g_lnpart[jj][tid][1] = h0 * h0 + h1 * h1 + h2 * h2 + h3 * h3;
    }
}

// phase B: heads GEMM, 4 cols per block, LN(h) inline; register-prefetched fills
__device__ void doHeads(int q, int nx, float* scr,
                        const float* __restrict__ lnhg, const float* __restrict__ lnhb,
                        const float* __restrict__ Wrk, const float* __restrict__ Wwk,
                        const float* __restrict__ Wws, const float* __restrict__ Wer,
                        const float* __restrict__ Wad) {
    int tid = threadIdx.x;
    float* As = scr;           // [32][66]
    float* Ws = scr + 2112;    // [32][4]
    float* smean = scr + 2304; // 64
    float* srstd = scr + 2368; // 64
    if (tid < 64) {
        float s = 0.f, s2 = 0.f;
#pragma unroll 8
        for (int j = 0; j < 128; ++j) { s += g_lnpart[j][tid][0]; s2 += g_lnpart[j][tid][1]; }
        float m = s * (1.f / 512);
        smean[tid] = m;
        srstd[tid] = rsqrtf(s2 * (1.f / 512) - m * m + EPS);
    }
    __syncthreads();
    int m = tid >> 2, c = tid & 3;
    int ar0 = tid >> 3, ar1 = ar0 + 32, ak = (tid & 7) * 4;
    const float* wp = headrow(q * 4 + (tid >> 3), Wrk, Wwk, Wws, Wer, Wad);  // tid<32
    float acc = 0.f;
    float4 hv0, hv1, gv0, gv1, bv0, bv1, vwh;
    vwh = make_float4(0.f, 0.f, 0.f, 0.f);

#define LDH_CHUNK(kt_)                                                        \
    {                                                                         \
        hv0 = *(const float4*)&g_h[nx][ar0][(kt_) + ak];                      \
        hv1 = *(const float4*)&g_h[nx][ar1][(kt_) + ak];                      \
        gv0 = *(const float4*)&lnhg[(kt_) + ak];                              \
        bv0 = *(const float4*)&lnhb[(kt_) + ak];                              \
        gv1 = gv0; bv1 = bv0;                                                 \
        if (tid < 32 && wp) vwh = *(const float4*)(wp + (kt_) + ((tid & 7) * 4)); \
    }

    LDH_CHUNK(0)
    for (int kt = 0; kt < 512; kt += 32) {
        __syncthreads();
        {
            float mm = smean[ar0], rs = srstd[ar0];
            As[(ak + 0) * 66 + ar0] = (hv0.x - mm) * rs * gv0.x + bv0.x;
            As[(ak + 1) * 66 + ar0] = (hv0.y - mm) * rs * gv0.y + bv0.y;
            As[(ak + 2) * 66 + ar0] = (hv0.z - mm) * rs * gv0.z + bv0.z;
            As[(ak + 3) * 66 + ar0] = (hv0.w - mm) * rs * gv0.w + bv0.w;
            mm = smean[ar1]; rs = srstd[ar1];
            As[(ak + 0) * 66 + ar1] = (hv1.x - mm) * rs * gv1.x + bv1.x;
            As[(ak + 1) * 66 + ar1] = (hv1.y - mm) * rs * gv1.y + bv1.y;
            As[(ak + 2) * 66 + ar1] = (hv1.z - mm) * rs * gv1.z + bv1.z;
            As[(ak + 3) * 66 + ar1] = (hv1.w - mm) * rs * gv1.w + bv1.w;
        }
        if (tid < 32) {
            int c2 = tid >> 3, kq = (tid & 7) * 4;
            Ws[(kq + 0) * 4 + c2] = vwh.x; Ws[(kq + 1) * 4 + c2] = vwh.y;
            Ws[(kq + 2) * 4 + c2] = vwh.z; Ws[(kq + 3) * 4 + c2] = vwh.w;
        }
        if (kt + 32 < 512) LDH_CHUNK(kt + 32)
        __syncthreads();
#pragma unroll
        for (int k = 0; k < 32; ++k) acc += As[k * 66 + m] * Ws[k * 4 + c];
    }
#undef LDH_CHUNK
    g_head[m][q * 4 + c] = acc;
}

// phase C (blocks 64..127): proj, 16 cols per block, K=768; register-prefetched fills
__device__ void doProj(int p, int trow, float* scr, const float* __restrict__ Aouts,
                       const float* __restrict__ Wproj, const float* __restrict__ bproj,
                       float* __restrict__ out) {
    int tid = threadIdx.x;
    float* As = scr;          // [32][68]
    float* Ws = scr + 2176;   // [32][20]
    int r0 = (tid >> 3) * 2, c0 = (tid & 7) * 2;
    int ar0 = tid >> 3, ar1 = ar0 + 32, ak = (tid & 7) * 4;
    int wc = tid >> 3, wk = (tid & 7) * 4;
    float a00 = 0.f, a01 = 0.f, a10 = 0.f, a11 = 0.f;
    float4 va0, va1, vw;
    vw = make_float4(0.f, 0.f, 0.f, 0.f);

#define LDP_CHUNK(kt_)                                                                 \
    {                                                                                  \
        va0 = *(const float4*)&Aouts[ar0 * 768 + (kt_) + ak];                          \
        va1 = *(const float4*)&Aouts[ar1 * 768 + (kt_) + ak];                          \
        if (tid < 128) vw = *(const float4*)&Wproj[(size_t)(16 * p + wc) * 768 + (kt_) + wk]; \
    }

    LDP_CHUNK(0)
    for (int kt = 0; kt < 768; kt += 32) {
        __syncthreads();
        As[(ak + 0) * 68 + ar0] = va0.x; As[(ak + 1) * 68 + ar0] = va0.y;
        As[(ak + 2) * 68 + ar0] = va0.z; As[(ak + 3) * 68 + ar0] = va0.w;
        As[(ak + 0) * 68 + ar1] = va1.x; As[(ak + 1) * 68 + ar1] = va1.y;
        As[(ak + 2) * 68 + ar1] = va1.z; As[(ak + 3) * 68 + ar1] = va1.w;
        if (tid < 128) {
            Ws[(wk + 0) * 20 + wc] = vw.x; Ws[(wk + 1) * 20 + wc] = vw.y;
            Ws[(wk + 2) * 20 + wc] = vw.z; Ws[(wk + 3) * 20 + wc] = vw.w;
        }
        if (kt + 32 < 768) LDP_CHUNK(kt + 32)
        __syncthreads();
#pragma unroll
        for (int k = 0; k < 32; ++k) {
            float2 a = *(const float2*)&As[k * 68 + r0];
            float2 w = *(const float2*)&Ws[k * 20 + c0];
            a00 += a.x * w.x; a01 += a.x * w.y; a10 += a.y * w.x; a11 += a.y * w.y;
        }
    }
#undef LDP_CHUNK
    int col = 16 * p + c0;
    float b0 = bproj[col], b1 = bproj[col + 1];
    out[((size_t)(r0 + 0) * cL + trow) * cO + col]     = a00 + b0;
    out[((size_t)(r0 + 0) * cL + trow) * cO + col + 1] = a01 + b1;
    out[((size_t)(r0 + 1) * cL + trow) * cO + col]     = a10 + b0;
    out[((size_t)(r0 + 1) * cL + trow) * cO + col + 1] = a11 + b1;
}

// phase C (blocks 0..63): memory write/read + outln + next ci
__device__ void doMem(int t, int b, float* s_mem, float* scr, const float* __restrict__ x,
                      const float* __restrict__ brk, const float* __restrict__ bwk,
                      const float* __restrict__ bws, const float* __restrict__ ber,
                      const float* __restrict__ bad,
                      const float* __restrict__ lnhg, const float* __restrict__ lnhb,
                      const float* __restrict__ lnrkg, const float* __restrict__ lnrkb,
                      const float* __restrict__ lnwkg, const float* __restrict__ lnwkb,
                      const float* __restrict__ lnmg, const float* __restrict__ lnmb,
                      const float* __restrict__ lnog, const float* __restrict__ lnob,
                      const float* __restrict__ lning, const float* __restrict__ lninb) {
    float* s_hn = scr;           // 512
    float* s_rk = scr + 512;     // 256
    float* s_wk = scr + 768;     // 64
    float* s_er = scr + 832;     // 64
    float* s_ad = scr + 896;     // 64
    float* s_wkln = scr + 960;   // 64
    float* s_rkln = scr + 1024;  // 256
    float* s_wsc = scr + 1280;   // 256
    float* s_rsc = scr + 1536;   // 1024
    float* s_rv = scr + 2560;    // 256
    float* red = scr + 2816;     // 8
    float* misc = scr + 2824;    // 4
    int tid = threadIdx.x, warp = tid >> 5, lane = tid & 31;
    int nx = (t + 1) & 1, ob = t & 1;

    if (tid < 32) {
        float s = 0.f, s2 = 0.f;
#pragma unroll
        for (int j = 0; j < 4; ++j) {
            s += g_lnpart[lane * 4 + j][b][0];
            s2 += g_lnpart[lane * 4 + j][b][1];
        }
#pragma unroll
        for (int o = 16; o; o >>= 1) {
            s += __shfl_xor_sync(0xffffffffu, s, o);
            s2 += __shfl_xor_sync(0xffffffffu, s2, o);
        }
        if (tid == 0) {
            float m = s * (1.f / 512);
            misc[1] = m;
            misc[2] = rsqrtf(s2 * (1.f / 512) - m * m + EPS);
        }
    }
    __syncthreads();
    float hm = misc[1], hrs = misc[2];
#pragma unroll
    for (int u = 0; u < 2; ++u) {
        int k = tid + u * 256;
        s_hn[k] = (g_h[nx][b][k] - hm) * hrs * lnhg[k] + lnhb[k];
    }
    for (int j = tid; j < 449; j += 256) {
        float v = g_head[b][j];
        if (j < 256) s_rk[j] = v + brk[j];
        else if (j < 320) s_wk[j - 256] = v + bwk[j - 256];
        else if (j == 320) misc[0] = sigf(v + bws[0]);
        else if (j < 385) s_er[j - 321] = sigf(v + ber[j - 321]);
        else s_ad[j - 385] = tanhf(v + bad[j - 385]);
    }
    __syncthreads();
    if (warp == 0) {
        float x0 = s_wk[lane], x1 = s_wk[lane + 32], s = x0 + x1;
#pragma unroll
        for (int o = 16; o; o >>= 1) s += __shfl_xor_sync(0xffffffffu, s, o);
        float mean = s * (1.f / 64), d0 = x0 - mean, d1 = x1 - mean;
        float vs = d0 * d0 + d1 * d1;
#pragma unroll
        for (int o = 16; o; o >>= 1) vs += __shfl_xor_sync(0xffffffffu, vs, o);
        float rs = rsqrtf(vs * (1.f / 64) + EPS);
        s_wkln[lane] = d0 * rs * lnwkg[lane] + lnwkb[lane];
        s_wkln[lane + 32] = d1 * rs * lnwkg[lane + 32] + lnwkb[lane + 32];
    } else if (warp <= 4) {
        int r = warp - 1;
        float x0 = s_rk[r * 64 + lane], x1 = s_rk[r * 64 + lane + 32], s = x0 + x1;
#pragma unroll
        for (int o = 16; o; o >>= 1) s += __shfl_xor_sync(0xffffffffu, s, o);
        float mean = s * (1.f / 64), d0 = x0 - mean, d1 = x1 - mean;
        float vs = d0 * d0 + d1 * d1;
#pragma unroll
        for (int o = 16; o; o >>= 1) vs += __shfl_xor_sync(0xffffffffu, vs, o);
        float rs = rsqrtf(vs * (1.f / 64) + EPS);
        s_rkln[r * 64 + lane] = d0 * rs * lnrkg[lane] + lnrkb[lane];
        s_rkln[r * 64 + lane + 32] = d1 * rs * lnrkg[lane + 32] + lnrkb[lane + 32];
    }
    __syncthreads();
    float mg0 = lnmg[lane], mg1 = lnmg[lane + 32];
    float mb0 = lnmb[lane], mb1 = lnmb[lane + 32];
    float wkl0 = s_wkln[lane], wkl1 = s_wkln[lane + 32];
    for (int m = warp; m < cM; m += 8) {
        float x0 = s_mem[m * 64 + lane], x1 = s_mem[m * 64 + lane + 32], s = x0 + x1;
#pragma unroll
        for (int o = 16; o; o >>= 1) s += __shfl_xor_sync(0xffffffffu, s, o);
        float mean = s * (1.f / 64), d0 = x0 - mean, d1 = x1 - mean;
        float vs = d0 * d0 + d1 * d1;
#pragma unroll
        for (int o = 16; o; o >>= 1) vs += __shfl_xor_sync(0xffffffffu, vs, o);
        float rs = rsqrtf(vs * (1.f / 64) + EPS);
        float dot = (d0 * rs * mg0 + mb0) * wkl0 + (d1 * rs * mg1 + mb1) * wkl1;
#pragma unroll
        for (int o = 16; o; o >>= 1) dot += __shfl_xor_sync(0xffffffffu, dot, o);
        if (lane == 0) s_wsc[m] = dot;
    }
    __syncthreads();
    {
        float v = s_wsc[tid];
        float mx = brmax(v, red);
        float e = expf(v - mx);
        float su = brsum(e, red);
        s_wsc[tid] = e / su * misc[0];
    }
    __syncthreads();
    for (int i = tid; i < cM * cHD; i += 256) {
        int m = i >> 6, hh = i & 63;
        float w = s_wsc[m];
        s_mem[i] = s_mem[i] * (1.f - w * s_er[hh]) + w * s_ad[hh];
    }
    __syncthreads();
    for (int m = warp; m < cM; m += 8) {
        float x0 = s_mem[m * 64 + lane], x1 = s_mem[m * 64 + lane + 32], s = x0 + x1;
#pragma unroll
        for (int o = 16; o; o >>= 1) s += __shfl_xor_sync(0xffffffffu, s, o);
        float mean = s * (1.f / 64), d0 = x0 - mean, d1 = x1 - mean;
        float vs = d0 * d0 + d1 * d1;
#pragma unroll
        for (int o = 16; o; o >>= 1) vs += __shfl_xor_sync(0xffffffffu, vs, o);
        float rs = rsqrtf(vs * (1.f / 64) + EPS);
        float n0 = d0 * rs * mg0 + mb0, n1 = d1 * rs * mg1 + mb1;
#pragma unroll
        for (int r = 0; r < 4; ++r) {
            float a = n0 * s_rkln[r * 64 + lane] + n1 * s_rkln[r * 64 + lane + 32];
#pragma unroll
            for (int o = 16; o; o >>= 1) a += __shfl_xor_sync(0xffffffffu, a, o);
            if (lane == 0) s_rsc[r * 256 + m] = a;
        }
    }
    __syncthreads();
#pragma unroll
    for (int r = 0; r < 4; ++r) {
        float v = s_rsc[r * 256 + tid];
        float mx = brmax(v, red);
        float e = expf(v - mx);
        float su = brsum(e, red);
        s_rsc[r * 256 + tid] = e / su;
    }
    __syncthreads();
    {
        int r = tid >> 6, hh = tid & 63;
        float a0 = 0.f, a1 = 0.f, a2 = 0.f, a3 = 0.f;
#pragma unroll 4
        for (int m = 0; m < cM; m += 4) {
            a0 += s_rsc[r * 256 + m + 0] * s_mem[(m + 0) * 64 + hh];
            a1 += s_rsc[r * 256 + m + 1] * s_mem[(m + 1) * 64 + hh];
            a2 += s_rsc[r * 256 + m + 2] * s_mem[(m + 2) * 64 + hh];
            a3 += s_rsc[r * 256 + m + 3] * s_mem[(m + 3) * 64 + hh];
        }
        s_rv[tid] = (a0 + a1) + (a2 + a3);
    }
    __syncthreads();
    {
        float o0 = s_hn[tid], o1 = s_hn[tid + 256], o2 = s_rv[tid];
        float mean = brsum(o0 + o1 + o2, red) * (1.f / cTO);
        float d0 = o0 - mean, d1 = o1 - mean, d2 = o2 - mean;
        float var = brsum(d0 * d0 + d1 * d1 + d2 * d2, red) * (1.f / cTO);
        float rs = rsqrtf(var + EPS);
        g_outln[ob][b][tid] = d0 * rs * lnog[tid] + lnob[tid];
        g_outln[ob][b][tid + 256] = d1 * rs * lnog[tid + 256] + lnob[tid + 256];
        g_outln[ob][b][tid + 512] = d2 * rs * lnog[tid + 512] + lnob[tid + 512];
    }
    if (t + 1 < cL) {
        const float* xn = x + ((size_t)b * cL + t + 1) * cE;
        float a0 = xn[tid], a1 = s_rv[tid];
        float mean = brsum(a0 + a1, red) * (1.f / cCI);
        float d0 = a0 - mean, d1 = a1 - mean;
        float var = brsum(d0 * d0 + d1 * d1, red) * (1.f / cCI);
        float rs = rsqrtf(var + EPS);
        g_ci[b][tid] = d0 * rs * lning[tid] + lninb[tid];
        g_ci[b][tid + 256] = d1 * rs * lning[tid + 256] + lninb[tid + 256];
    }
}

__global__ void __launch_bounds__(256, 1) k_persist(
    const float* __restrict__ x, const float* __restrict__ Wih,
    const float* __restrict__ Whh, const float* __restrict__ bih,
    const float* __restrict__ bhh, const float* __restrict__ lning,
    const float* __restrict__ lninb, const float* __restrict__ lnhg,
    const float* __restrict__ lnhb, const float* __restrict__ Wrk,
    const float* __restrict__ brk, const float* __restrict__ Wwk,
    const float* __restrict__ bwk, const float* __restrict__ Wws,
    const float* __restrict__ bws, const float* __restrict__ Wer,
    const float* __restrict__ ber, const float* __restrict__ Wad,
    const float* __restrict__ bad, const float* __restrict__ lnrkg,
    const float* __restrict__ lnrkb, const float* __restrict__ lnwkg,
    const float* __restrict__ lnwkb, const float* __restrict__ lnmg,
    const float* __restrict__ lnmb, const float* __restrict__ lnog,
    const float* __restrict__ lnob, const float* __restrict__ Wproj,
    const float* __restrict__ bproj, float* __restrict__ out,
    float* __restrict__ memg, float* __restrict__ hout, float* __restrict__ cout) {
    extern __shared__ float sm[];
    float* s_mem = sm;          // 16384 (persistent memory, blocks 0..63)
    float* scr = sm + 16384;    // 4096 scratch
    int bx = blockIdx.x, tid = threadIdx.x;

    if (bx < 64) {
        for (int i = tid; i < cM * cHD; i += 256) s_mem[i] = 0.f;
        int b = bx;
#pragma unroll
        for (int u = 0; u < 2; ++u) {
            int k = tid + u * 256;
            g_c[b][k] = 0.f;
            g_h[0][b][k] = 0.f;
        }
        float* red = scr;
        float a0 = x[(size_t)b * cL * cE + tid];
        float mean = brsum(a0, red) * (1.f / cCI);
        float d0 = a0 - mean, d1 = -mean;
        float var = brsum(d0 * d0 + d1 * d1, red) * (1.f / cCI);
        float rs = rsqrtf(var + EPS);
        g_ci[b][tid] = d0 * rs * lning[tid] + lninb[tid];
        g_ci[b][tid + 256] = d1 * rs * lning[tid + 256] + lninb[tid + 256];
    }
    gsync();

    for (int t = 0; t < cL; ++t) {
        doA(t, scr, Wih, Whh, bih, bhh);
        gsync();
        doHeads(bx, (t + 1) & 1, scr, lnhg, lnhb, Wrk, Wwk, Wws, Wer, Wad);
        gsync();
        if (bx < 64) {
            doMem(t, bx, s_mem, scr, x, brk, bwk, bws, ber, bad, lnhg, lnhb,
                  lnrkg, lnrkb, lnwkg, lnwkb, lnmg, lnmb, lnog, lnob, lning, lninb);
        } else if (t > 0) {
            doProj(bx - 64, t - 1, scr, &g_outln[(t - 1) & 1][0][0], Wproj, bproj, out);
        }
        gsync();
    }
    if (bx >= 64) {
        doProj(bx - 64, cL - 1, scr, &g_outln[(cL - 1) & 1][0][0], Wproj, bproj, out);
    } else {
        int b = bx;
        for (int i = tid; i < cM * cHD; i += 256) memg[(size_t)b * cM * cHD + i] = s_mem[i];
#pragma unroll
        for (int u = 0; u < 2; ++u) {
            int k = tid + u * 256;
            hout[b * cH + k] = g_h[0][b][k];
            cout[b * cH + k] = g_c[b][k];
        }
    }
}

extern "C" void kernel_launch(void* const* d_in, const int* in_sizes, int n_in,
                              void* d_out, int out_size) {
    const float** p = (const float**)d_in;
    float* out = (float*)d_out;
    float* memg = out + (size_t)cB * cL * cO;
    float* hout = memg + (size_t)cB * cM * cHD;
    float* cout = hout + (size_t)cB * cH;
    const int smem = (16384 + 4096) * 4;
    cudaFuncSetAttribute(k_persist, cudaFuncAttributeMaxDynamicSharedMemorySize, smem);
    k_persist<<<NBLK, 256, smem>>>(p[0], p[1], p[2], p[3], p[4], p[5], p[6], p[7], p[8],
                                   p[9], p[10], p[11], p[12], p[13], p[14], p[15], p[16],
                                   p[17], p[18], p[19], p[20], p[21], p[22], p[23], p[24],
                                   p[25], p[26], p[27], p[28], out, memg, hout, cout);
}